// round 12
// baseline (speedup 1.0000x reference)
#include <cuda_runtime.h>
#include <math.h>

// ---------------------------------------------------------------------------
// Balanced Sinkhorn, persistent single-kernel, zero per-row FP64.
// E' = exp((f - colmax)/eps) in [0,1] (column shift exactly invariant: the
// reference row-normalizes first) lives entirely in shared memory.
// Per-row scalars factored as r = 1/c so all products stay in fp32 range.
// R12: contention-free broadcast-flag grid barrier (each block polls its OWN
// 128B-padded flag; releaser broadcasts with 148 parallel st.release) replacing
// the single-address spin that had 147 SMs hammering one LTS slice.
// ---------------------------------------------------------------------------

#define NB 16384
#define NK 256
#define GRID_P 148
#define BLOCK_P 512
#define WARPS_P 16
#define N_OUTER 10
#define INV_B 6.103515625e-05f   // 1/16384 (exact)
#define CHUNK 4
#define STRIDE (WARPS_P * CHUNK)   // 64
#define CHUNK2 2
#define STRIDE2 (WARPS_P * CHUNK2) // 32

// shared memory layout (bytes)
#define OFF_RED  0        // double[256]   2048
#define OFF_K2   2048     // double[256]   2048
#define OFF_R1   4096     // double[256]   2048
#define OFF_SCL  6144     // double[4]       64 (scalar broadcast)
#define OFF_BARS 6208     // unsigned[16]    64 (barrier scalar)
#define OFF_W    6272     // float[256]    1024
#define OFF_BUF  7296     // float[256]    1024
#define OFF_V1   8320     // float[112]     448
#define OFF_V2   8768     // float[112]     448
#define OFF_U    9216     // float[256]    1024
#define OFF_ACC  10240    // float[16*256] 16384
#define OFF_E    26624    // float[111*256] 113664
#define SMEM_TOTAL 140288

// Global state (allocation-free). Barrier counter/flags monotonic across graph
// replays (uniform fixed barrier count per launch); accumulators re-zeroed
// inside the kernel each launch; cmax idempotent.
static __device__ unsigned g_count;                              // arrivals
static __device__ __align__(128) unsigned g_flag[GRID_P * 32];   // 128B-padded
static __device__ unsigned g_cmax[NK];
static __device__ double g_R1[NK];
static __device__ double g_R2[2][NK], g_R3[2][NK];
static __device__ double g_ub1[2][NK], g_ub2[2][NK], g_ub3[2][NK];

__device__ __forceinline__ float frcp(float x) {
    float r; asm("rcp.approx.f32 %0, %1;" : "=f"(r) : "f"(x)); return r;
}
// fp32-seeded double reciprocal with one DP Newton step (~2^-46)
__device__ __forceinline__ double rcpd(double x) {
    double r = (double)frcp((float)x);
    return r * (2.0 - x * r);
}
__device__ __forceinline__ unsigned encf(float x) {
    unsigned u = __float_as_uint(x);
    return (u & 0x80000000u) ? ~u : (u | 0x80000000u);
}
__device__ __forceinline__ float decf(unsigned e) {
    unsigned u = (e & 0x80000000u) ? (e & 0x7fffffffu) : ~e;
    return __uint_as_float(u);
}

__device__ __forceinline__ double warpRedSumD(double v) {
#pragma unroll
    for (int m = 16; m; m >>= 1) v += __shfl_xor_sync(0xffffffffu, v, m);
    return v;
}
__device__ __forceinline__ float warpRedMaxF(float v) {
#pragma unroll
    for (int m = 16; m; m >>= 1) v = fmaxf(v, __shfl_xor_sync(0xffffffffu, v, m));
    return v;
}

// interleaved butterflies (pipeline SHFL latency across independent rows)
__device__ __forceinline__ void bflyN(float* c, int n) {
#pragma unroll
    for (int m = 16; m; m >>= 1)
        for (int i = 0; i < n; i++)
            c[i] += __shfl_xor_sync(0xffffffffu, c[i], m);
}

// ---------------------------------------------------------------------------
// Grid barrier, broadcast-flag design:
//  - arrival: one acq_rel RMW on g_count (orders this block's prior REDs and
//    pulls in peers' released writes at the releaser)
//  - release: LAST arriver's threads tid<GRID_P each st.release one per-block
//    flag (128B apart -> parallel across LTS slices, no hot address)
//  - wait: each block acquire-polls its OWN flag (1 poller per address)
// Monotonic epochs: old/GRID+1, poll >=. Safe across graph replays.
// ---------------------------------------------------------------------------
__device__ __forceinline__ void gridBar(unsigned* sbar, int tid, int bid) {
    __syncthreads();
    if (tid == 0) {
        unsigned t;
        asm volatile("atom.acq_rel.gpu.global.add.u32 %0, [%1], 1;"
                     : "=r"(t) : "l"(&g_count) : "memory");
        *sbar = t;
    }
    __syncthreads();
    unsigned t = *sbar;
    unsigned epoch = t / GRID_P + 1u;
    if ((t % GRID_P) == GRID_P - 1u) {          // this block is the releaser
        if (tid < GRID_P)
            asm volatile("st.release.gpu.global.u32 [%0], %1;"
                         :: "l"(&g_flag[tid * 32]), "r"(epoch) : "memory");
    }
    if (tid == 0) {
        unsigned v;
        do {
            asm volatile("ld.acquire.gpu.global.u32 %0, [%1];"
                         : "=r"(v) : "l"(&g_flag[bid * 32]) : "memory");
        } while (v < epoch);
    }
    __syncthreads();
}

// per-warp fp32 partials -> block fp32 -> global fp64 atomic
__device__ __forceinline__ void blockAcc(float* sacc, const float a[8],
                                         int lane, int warp, int tid,
                                         double* gdst) {
    float4* dst = (float4*)(sacc + warp * NK);
    dst[lane]      = make_float4(a[0], a[1], a[2], a[3]);
    dst[32 + lane] = make_float4(a[4], a[5], a[6], a[7]);
    __syncthreads();
    if (tid < NK) {
        float s = 0.f;
#pragma unroll
        for (int w = 0; w < WARPS_P; w++) s += sacc[w * NK + tid];
        atomicAdd(&gdst[tid], (double)s);
    }
}

// fwd: c[b]=sum u*E; r=1/c stored; Rout[k] += E*(r/B). E retained in regs.
__device__ __forceinline__ void fwdBody(const float* sE, const float* su,
                                        float* svf, int nrows, double* Rout,
                                        float* sacc, int lane, int warp, int tid) {
    float4 u0 = ((const float4*)su)[lane];
    float4 u1 = ((const float4*)su)[32 + lane];
    float a[8];
#pragma unroll
    for (int i = 0; i < 8; i++) a[i] = 0.f;
    for (int lr0 = warp * CHUNK; lr0 < nrows; lr0 += STRIDE) {
        float4 E0[CHUNK], E1[CHUNK];
        float c[CHUNK];
#pragma unroll
        for (int i = 0; i < CHUNK; i++) {
            if (lr0 + i < nrows) {
                const float4* row = (const float4*)(sE + (lr0 + i) * NK);
                E0[i] = row[lane]; E1[i] = row[32 + lane];
                c[i] = E0[i].x*u0.x + E0[i].y*u0.y + E0[i].z*u0.z + E0[i].w*u0.w
                     + E1[i].x*u1.x + E1[i].y*u1.y + E1[i].z*u1.z + E1[i].w*u1.w;
            } else {
                E0[i] = make_float4(0,0,0,0); E1[i] = E0[i]; c[i] = 1.f;
            }
        }
        bflyN(c, CHUNK);
#pragma unroll
        for (int i = 0; i < CHUNK; i++) {
            float r = frcp(fmaxf(c[i], 1e-37f));
            if (lane == 0 && lr0 + i < nrows) svf[lr0 + i] = r;
            float vf = r * INV_B;
            a[0] += E0[i].x*vf; a[1] += E0[i].y*vf; a[2] += E0[i].z*vf; a[3] += E0[i].w*vf;
            a[4] += E1[i].x*vf; a[5] += E1[i].y*vf; a[6] += E1[i].z*vf; a[7] += E1[i].w*vf;
        }
    }
    blockAcc(sacc, a, lane, warp, tid, Rout);
}

// passC (3rd fwd fused with bwd layer 3), CHUNK2 with E,P retained:
//  c, s = sum u*E{,*P}; r=1/c; v3=r/B; cbar=(s*r)*v3; ub3 += E*(cbar - v3*P)
__device__ __forceinline__ void passCBody(const float* sE, const float* su,
                                          const float* __restrict__ fin, int rs,
                                          int nrows, double* gdst, float* sacc,
                                          int lane, int warp, int tid) {
    float4 u0 = ((const float4*)su)[lane];
    float4 u1 = ((const float4*)su)[32 + lane];
    float a[8];
#pragma unroll
    for (int i = 0; i < 8; i++) a[i] = 0.f;
    for (int lr0 = warp * CHUNK2; lr0 < nrows; lr0 += STRIDE2) {
        float4 E0[CHUNK2], E1[CHUNK2], P0[CHUNK2], P1[CHUNK2];
        float c[CHUNK2], s[CHUNK2];
#pragma unroll
        for (int i = 0; i < CHUNK2; i++) {
            if (lr0 + i < nrows) {
                const float4* row  = (const float4*)(sE + (lr0 + i) * NK);
                const float4* frow = (const float4*)(fin + (size_t)(rs + lr0 + i) * NK);
                E0[i] = row[lane]; E1[i] = row[32 + lane];
                P0[i] = frow[lane]; P1[i] = frow[32 + lane];
                float t00 = E0[i].x*u0.x, t01 = E0[i].y*u0.y,
                      t02 = E0[i].z*u0.z, t03 = E0[i].w*u0.w;
                float t10 = E1[i].x*u1.x, t11 = E1[i].y*u1.y,
                      t12 = E1[i].z*u1.z, t13 = E1[i].w*u1.w;
                c[i] = t00+t01+t02+t03 + t10+t11+t12+t13;
                s[i] = t00*P0[i].x + t01*P0[i].y + t02*P0[i].z + t03*P0[i].w
                     + t10*P1[i].x + t11*P1[i].y + t12*P1[i].z + t13*P1[i].w;
            } else {
                E0[i] = make_float4(0,0,0,0); E1[i] = E0[i];
                P0[i] = E0[i]; P1[i] = E0[i];
                c[i] = 1.f; s[i] = 0.f;
            }
        }
        bflyN(c, CHUNK2);
        bflyN(s, CHUNK2);
#pragma unroll
        for (int i = 0; i < CHUNK2; i++) {
            float r = frcp(fmaxf(c[i], 1e-37f));
            float v3f = r * INV_B;
            float cbf = (s[i] * r) * v3f;     // = B*v3^2*s, overflow-safe order
            a[0] += E0[i].x*(cbf - v3f*P0[i].x); a[1] += E0[i].y*(cbf - v3f*P0[i].y);
            a[2] += E0[i].z*(cbf - v3f*P0[i].z); a[3] += E0[i].w*(cbf - v3f*P0[i].w);
            a[4] += E1[i].x*(cbf - v3f*P1[i].x); a[5] += E1[i].y*(cbf - v3f*P1[i].y);
            a[6] += E1[i].z*(cbf - v3f*P1[i].z); a[7] += E1[i].w*(cbf - v3f*P1[i].w);
        }
    }
    blockAcc(sacc, a, lane, warp, tid, gdst);
}

// bwd layer: t[b]=sum rb*E; cb=-(t*r)*(r/B); ub_out += E*cb. E retained.
__device__ __forceinline__ void bwdBody(const float* sE, const float* su,
                                        const float* svf, int nrows, double* gdst,
                                        float* sacc, int lane, int warp, int tid) {
    float4 b0 = ((const float4*)su)[lane];
    float4 b1 = ((const float4*)su)[32 + lane];
    float a[8];
#pragma unroll
    for (int i = 0; i < 8; i++) a[i] = 0.f;
    for (int lr0 = warp * CHUNK; lr0 < nrows; lr0 += STRIDE) {
        float4 E0[CHUNK], E1[CHUNK];
        float t[CHUNK];
#pragma unroll
        for (int i = 0; i < CHUNK; i++) {
            if (lr0 + i < nrows) {
                const float4* row = (const float4*)(sE + (lr0 + i) * NK);
                E0[i] = row[lane]; E1[i] = row[32 + lane];
                t[i] = E0[i].x*b0.x + E0[i].y*b0.y + E0[i].z*b0.z + E0[i].w*b0.w
                     + E1[i].x*b1.x + E1[i].y*b1.y + E1[i].z*b1.z + E1[i].w*b1.w;
            } else {
                E0[i] = make_float4(0,0,0,0); E1[i] = E0[i]; t[i] = 0.f;
            }
        }
        bflyN(t, CHUNK);
#pragma unroll
        for (int i = 0; i < CHUNK; i++) {
            float r = (lr0 + i < nrows) ? svf[lr0 + i] : 0.f;
            float cbf = -(t[i] * r) * (r * INV_B);   // = -B*v^2*t
            a[0] += E0[i].x*cbf; a[1] += E0[i].y*cbf; a[2] += E0[i].z*cbf; a[3] += E0[i].w*cbf;
            a[4] += E1[i].x*cbf; a[5] += E1[i].y*cbf; a[6] += E1[i].z*cbf; a[7] += E1[i].w*cbf;
        }
    }
    blockAcc(sacc, a, lane, warp, tid, gdst);
}

// output: Q = E * (B*v3) * u3, fp32; r refined with one fp32 Newton. Retained E.
__device__ __forceinline__ void outBody(const float* sE, const float* su,
                                        float* __restrict__ out, int rs,
                                        int nrows, int lane, int warp) {
    float4 u0 = ((const float4*)su)[lane];
    float4 u1 = ((const float4*)su)[32 + lane];
    for (int lr0 = warp * CHUNK; lr0 < nrows; lr0 += STRIDE) {
        float4 E0[CHUNK], E1[CHUNK];
        float c[CHUNK];
#pragma unroll
        for (int i = 0; i < CHUNK; i++) {
            if (lr0 + i < nrows) {
                const float4* row = (const float4*)(sE + (lr0 + i) * NK);
                E0[i] = row[lane]; E1[i] = row[32 + lane];
                c[i] = E0[i].x*u0.x + E0[i].y*u0.y + E0[i].z*u0.z + E0[i].w*u0.w
                     + E1[i].x*u1.x + E1[i].y*u1.y + E1[i].z*u1.z + E1[i].w*u1.w;
            } else {
                E0[i] = make_float4(0,0,0,0); E1[i] = E0[i]; c[i] = 1.f;
            }
        }
        bflyN(c, CHUNK);
#pragma unroll
        for (int i = 0; i < CHUNK; i++) {
            int lr = lr0 + i;
            if (lr < nrows) {
                float cc = fmaxf(c[i], 1e-37f);
                float r0 = frcp(cc);
                float bs = r0 * (2.0f - cc * r0);  // refined 1/c = B*v3
                float4 o0, o1;
                o0.x = (E0[i].x*bs)*u0.x; o0.y = (E0[i].y*bs)*u0.y;
                o0.z = (E0[i].z*bs)*u0.z; o0.w = (E0[i].w*bs)*u0.w;
                o1.x = (E1[i].x*bs)*u1.x; o1.y = (E1[i].y*bs)*u1.y;
                o1.z = (E1[i].z*bs)*u1.z; o1.w = (E1[i].w*bs)*u1.w;
                float4* orow = (float4*)(out + (size_t)(rs + lr) * NK);
                orow[lane] = o0;
                orow[32 + lane] = o1;
            }
        }
    }
}

__global__ void __launch_bounds__(BLOCK_P, 1)
sinkhorn_persist(const float* __restrict__ fin, const float* __restrict__ win,
                 float* __restrict__ out) {
    extern __shared__ char smem[];
    double*   sred = (double*)(smem + OFF_RED);
    double*   sK2  = (double*)(smem + OFF_K2);
    double*   sR1  = (double*)(smem + OFF_R1);
    double*   sscl = (double*)(smem + OFF_SCL);
    unsigned* sbar = (unsigned*)(smem + OFF_BARS);
    float*    sw   = (float*) (smem + OFF_W);
    float*    sbuf = (float*) (smem + OFF_BUF);
    float*    sv1  = (float*) (smem + OFF_V1);
    float*    sv2  = (float*) (smem + OFF_V2);
    float*    su   = (float*) (smem + OFF_U);
    float*    sacc = (float*) (smem + OFF_ACC);
    float*    sE   = (float*) (smem + OFF_E);

    const int tid  = threadIdx.x;
    const int lane = tid & 31, warp = tid >> 5;
    const int bid  = blockIdx.x;
    const int rs = (NB * bid) / GRID_P;
    const int re = (NB * (bid + 1)) / GRID_P;
    const int nrows = re - rs;

    // ---- phase A: zero globals (block 0); load w; softmax(w) -> sK2 (all);
    //      stage raw f into smem E area + column-max partials ----
    if (bid == 0 && tid < NK) {
        __stcg(&g_R1[tid], 0.0);
#pragma unroll
        for (int s2 = 0; s2 < 2; s2++) {
            __stcg(&g_R2[s2][tid], 0.0);  __stcg(&g_R3[s2][tid], 0.0);
            __stcg(&g_ub1[s2][tid], 0.0); __stcg(&g_ub2[s2][tid], 0.0);
            __stcg(&g_ub3[s2][tid], 0.0);
        }
    }
    if (tid < NK) { float wv = win[tid]; sw[tid] = wv; sbuf[tid] = 0.f; su[tid] = wv; }
    __syncthreads();
    if (warp == 0) {
        float m = -3.4e38f;
#pragma unroll
        for (int i = 0; i < 8; i++) m = fmaxf(m, su[lane + 32*i]);
        m = warpRedMaxF(m);
        if (lane == 0) sscl[0] = (double)m;
    }
    __syncthreads();
    {   float m = (float)sscl[0];
        float ex = 0.f;
        if (tid < NK) { ex = expf(sw[tid] - m); sred[tid] = (double)ex; }
        __syncthreads();
        if (warp == 0) {
            double s = 0.0;
#pragma unroll
            for (int i = 0; i < 8; i++) s += sred[lane + 32*i];
            s = warpRedSumD(s);
            if (lane == 0) sscl[0] = s;
        }
        __syncthreads();
        float ssum = (float)sscl[0];
        if (tid < NK) sK2[tid] = (double)(ex / ssum);
    }
    {   // stage f into smem + column max (thread = (col, row-half))
        int col = tid & 255, half = tid >> 8;
        float mx = -3.4e38f;
        for (int r = rs + half; r < re; r += 2) {
            float f = fin[(size_t)r * NK + col];
            sE[(r - rs) * NK + col] = f;
            mx = fmaxf(mx, f);
        }
        atomicMax(&g_cmax[col], encf(mx));   // idempotent across replays
    }
    gridBar(sbar, tid, bid);

    // ---- phase B: E' = exp((f-colmax)*20) in place; R1 = colsum ----
    {
        int col = tid & 255, half = tid >> 8;
        float Mt = decf(__ldcg(&g_cmax[col]));
        float r1p = 0.f;
        for (int r = rs + half; r < re; r += 2) {
            float e = expf((sE[(r - rs) * NK + col] - Mt) * 20.0f);
            sE[(r - rs) * NK + col] = e;
            r1p += e;
        }
        atomicAdd(&g_R1[col], (double)r1p);
    }
    gridBar(sbar, tid, bid);
    if (tid < NK) sR1[tid] = __ldcg(&g_R1[tid]);
    __syncthreads();

    // ---- outer loop ----
    for (int it = 0; it < N_OUTER; ++it) {
        const int s = it & 1;
        const bool last = (it == N_OUTER - 1);

        // fwd1: u1 = K2/R1 -> sv1, R2[s]
        if (tid < NK) su[tid] = (float)sK2[tid] / (float)sR1[tid];
        __syncthreads();
        fwdBody(sE, su, sv1, nrows, g_R2[s], sacc, lane, warp, tid);
        gridBar(sbar, tid, bid);

        // zero next iteration's accumulator slot (block 0; double-buffered:
        // slot s^1 was last read before this barrier, next written 2 bars later)
        if (bid == 0 && !last && tid < NK) {
            int t2 = s ^ 1;
            __stcg(&g_R2[t2][tid], 0.0);  __stcg(&g_R3[t2][tid], 0.0);
            __stcg(&g_ub1[t2][tid], 0.0); __stcg(&g_ub2[t2][tid], 0.0);
            __stcg(&g_ub3[t2][tid], 0.0);
        }

        // fwd2: u2 = K2/R2 -> sv2, R3[s]
        if (tid < NK) su[tid] = (float)sK2[tid] / (float)__ldcg(&g_R2[s][tid]);
        __syncthreads();
        fwdBody(sE, su, sv2, nrows, g_R3[s], sacc, lane, warp, tid);
        gridBar(sbar, tid, bid);

        if (!last) {
            // passC: u3 = K2/R3 -> ub3[s]
            if (tid < NK) su[tid] = (float)sK2[tid] / (float)__ldcg(&g_R3[s][tid]);
            __syncthreads();
            passCBody(sE, su, fin, rs, nrows, g_ub3[s], sacc, lane, warp, tid);
            gridBar(sbar, tid, bid);

            // bwd layer 2: rb = -ub3*K2/R3^2 (K-side DP), uses sv2 -> ub2[s]
            if (tid < NK) {
                double R = __ldcg(&g_R3[s][tid]);
                double rd = (double)frcp((float)R);
                su[tid] = (float)((-__ldcg(&g_ub3[s][tid]) * sK2[tid] * rd) * rd);
            }
            __syncthreads();
            bwdBody(sE, su, sv2, nrows, g_ub2[s], sacc, lane, warp, tid);
            gridBar(sbar, tid, bid);

            // bwd layer 1: rb = -ub2*K2/R2^2, uses sv1 -> ub1[s]
            if (tid < NK) {
                double R = __ldcg(&g_R2[s][tid]);
                double rd = (double)frcp((float)R);
                su[tid] = (float)((-__ldcg(&g_ub2[s][tid]) * sK2[tid] * rd) * rd);
            }
            __syncthreads();
            bwdBody(sE, su, sv1, nrows, g_ub1[s], sacc, lane, warp, tid);
            gridBar(sbar, tid, bid);

            // ---- SGD update, redundant per block, warp-reduced ----
            double K2j = 0.0, kb = 0.0;
            if (tid < NK) {
                K2j = sK2[tid];
                kb = __ldcg(&g_ub1[s][tid]) * rcpd(sR1[tid])
                   + __ldcg(&g_ub2[s][tid]) * rcpd(__ldcg(&g_R2[s][tid]))
                   + __ldcg(&g_ub3[s][tid]) * rcpd(__ldcg(&g_R3[s][tid]));
                sred[tid] = kb * K2j;
            }
            __syncthreads();
            if (warp == 0) {
                double d = 0.0;
#pragma unroll
                for (int i = 0; i < 8; i++) d += sred[lane + 32*i];
                d = warpRedSumD(d);
                if (lane == 0) sscl[0] = d;
            }
            __syncthreads();
            double dot = sscl[0];
            float gf = 0.f;
            if (tid < NK) {
                double g = K2j*(kb - dot) + 5.0*(K2j*(1.0/256.0) - (1.0/65536.0));
                gf = (float)g;
                sred[tid] = (double)gf * (double)gf;
            }
            __syncthreads();
            if (warp == 0) {
                double d = 0.0;
#pragma unroll
                for (int i = 0; i < 8; i++) d += sred[lane + 32*i];
                d = warpRedSumD(d);
                if (lane == 0) sscl[0] = sqrt(d);
            }
            __syncthreads();
            float norm = (float)sscl[0];
            if (tid < NK) {
                gf *= fminf(1.0f, 1.0f/(norm + 1e-6f));
                float bf = 0.99f*sbuf[tid] + gf; sbuf[tid] = bf;
                float wv = sw[tid] - 0.1f*bf;    sw[tid]   = wv;
                su[tid] = wv;
            }
            __syncthreads();
            if (warp == 0) {
                float m = -3.4e38f;
#pragma unroll
                for (int i = 0; i < 8; i++) m = fmaxf(m, su[lane + 32*i]);
                m = warpRedMaxF(m);
                if (lane == 0) sscl[0] = (double)m;
            }
            __syncthreads();
            float m = (float)sscl[0];
            float ex = 0.f;
            if (tid < NK) { ex = expf(sw[tid] - m); sred[tid] = (double)ex; }
            __syncthreads();
            if (warp == 0) {
                double d = 0.0;
#pragma unroll
                for (int i = 0; i < 8; i++) d += sred[lane + 32*i];
                d = warpRedSumD(d);
                if (lane == 0) sscl[0] = d;
            }
            __syncthreads();
            float ssum = (float)sscl[0];
            if (tid < NK) sK2[tid] = (double)(ex / ssum);
            __syncthreads();
        } else {
            // final: Q uses pre-update w
            if (tid < NK) su[tid] = (float)sK2[tid] / (float)__ldcg(&g_R3[s][tid]);
            __syncthreads();
            outBody(sE, su, out, rs, nrows, lane, warp);
        }
    }
}

// ---------------------------------------------------------------------------
extern "C" void kernel_launch(void* const* d_in, const int* in_sizes, int n_in,
                              void* d_out, int out_size) {
    const float* fin = nullptr;
    const float* win = nullptr;
    for (int i = 0; i < n_in; i++) {
        if (in_sizes[i] == NB*NK)   fin = (const float*)d_in[i];
        else if (in_sizes[i] == NK) win = (const float*)d_in[i];
    }
    if (!fin) fin = (const float*)d_in[0];
    if (!win) win = (const float*)d_in[1];
    float* out = (float*)d_out;

    cudaFuncSetAttribute(sinkhorn_persist,
                         cudaFuncAttributeMaxDynamicSharedMemorySize, SMEM_TOTAL);
    sinkhorn_persist<<<GRID_P, BLOCK_P, SMEM_TOTAL>>>(fin, win, out);
}

// round 13
// speedup vs baseline: 1.1299x; 1.1299x over previous
#include <cuda_runtime.h>
#include <math.h>

// ---------------------------------------------------------------------------
// Balanced Sinkhorn, persistent single-kernel, zero per-row FP64.
// E' = exp((f - colmax)/eps) in [0,1] (column shift exactly invariant: the
// reference row-normalizes first) lives entirely in shared memory.
// Per-row scalars factored as r = 1/c so all products stay in fp32 range.
// R13: all cross-block accumulators padded to ONE 256B L2 line per logical
// element (stride 32 doubles). Previously 148 blocks fired 256 fp64 REDs at 16
// cache lines -> ~16 LTS slices serialized ~2400 atomic ops each (~3-5us/pass,
// hidden inside the barrier's release ordering). Padding spreads the 256
// logical columns across all LTS slices; 256B (not 128B) avoids the
// transparent-bit-7 pair collision in the addr->LTS hash.
// ---------------------------------------------------------------------------

#define NB 16384
#define NK 256
#define GRID_P 148
#define BLOCK_P 512
#define WARPS_P 16
#define N_OUTER 10
#define INV_B 6.103515625e-05f   // 1/16384 (exact)
#define CHUNK 4
#define STRIDE (WARPS_P * CHUNK)   // 64
#define CHUNK2 2
#define STRIDE2 (WARPS_P * CHUNK2) // 32
#define GP  32   // accumulator pad: 32 doubles = 256 B per logical element
#define GPC 64   // cmax pad: 64 uints = 256 B

// shared memory layout (bytes)
#define OFF_RED  0        // double[256]   2048
#define OFF_K2   2048     // double[256]   2048
#define OFF_R1   4096     // double[256]   2048
#define OFF_SCL  6144     // double[4]       64 (scalar broadcast)
#define OFF_BARS 6208     // unsigned[16]    64 (barrier scalar)
#define OFF_W    6272     // float[256]    1024
#define OFF_BUF  7296     // float[256]    1024
#define OFF_V1   8320     // float[112]     448
#define OFF_V2   8768     // float[112]     448
#define OFF_U    9216     // float[256]    1024
#define OFF_ACC  10240    // float[16*256] 16384
#define OFF_E    26624    // float[111*256] 113664
#define SMEM_TOTAL 140288

// Global state (allocation-free). Barrier counter/flags monotonic across graph
// replays (uniform fixed barrier count per launch); accumulators re-zeroed
// inside the kernel each launch; cmax idempotent. All accumulators 256B-strided.
static __device__ unsigned g_count;                              // arrivals
static __device__ __align__(128) unsigned g_flag[GRID_P * 32];   // 128B-padded
static __device__ __align__(256) unsigned g_cmax[NK * GPC];
static __device__ __align__(256) double g_R1[NK * GP];
static __device__ __align__(256) double g_R2[2][NK * GP], g_R3[2][NK * GP];
static __device__ __align__(256) double g_ub1[2][NK * GP], g_ub2[2][NK * GP],
                                        g_ub3[2][NK * GP];

__device__ __forceinline__ float frcp(float x) {
    float r; asm("rcp.approx.f32 %0, %1;" : "=f"(r) : "f"(x)); return r;
}
// fp32-seeded double reciprocal with one DP Newton step (~2^-46)
__device__ __forceinline__ double rcpd(double x) {
    double r = (double)frcp((float)x);
    return r * (2.0 - x * r);
}
__device__ __forceinline__ unsigned encf(float x) {
    unsigned u = __float_as_uint(x);
    return (u & 0x80000000u) ? ~u : (u | 0x80000000u);
}
__device__ __forceinline__ float decf(unsigned e) {
    unsigned u = (e & 0x80000000u) ? (e & 0x7fffffffu) : ~e;
    return __uint_as_float(u);
}

__device__ __forceinline__ double warpRedSumD(double v) {
#pragma unroll
    for (int m = 16; m; m >>= 1) v += __shfl_xor_sync(0xffffffffu, v, m);
    return v;
}
__device__ __forceinline__ float warpRedMaxF(float v) {
#pragma unroll
    for (int m = 16; m; m >>= 1) v = fmaxf(v, __shfl_xor_sync(0xffffffffu, v, m));
    return v;
}

// interleaved butterflies (pipeline SHFL latency across independent rows)
__device__ __forceinline__ void bflyN(float* c, int n) {
#pragma unroll
    for (int m = 16; m; m >>= 1)
        for (int i = 0; i < n; i++)
            c[i] += __shfl_xor_sync(0xffffffffu, c[i], m);
}

// ---------------------------------------------------------------------------
// Grid barrier, broadcast-flag design (R12; kept — proven correct):
//  arrival acq_rel RMW on g_count; last arriver st.release's all per-block
//  flags (128B apart); each block acquire-polls its OWN flag.
// Monotonic epochs: old/GRID+1, poll >=. Safe across graph replays.
// ---------------------------------------------------------------------------
__device__ __forceinline__ void gridBar(unsigned* sbar, int tid, int bid) {
    __syncthreads();
    if (tid == 0) {
        unsigned t;
        asm volatile("atom.acq_rel.gpu.global.add.u32 %0, [%1], 1;"
                     : "=r"(t) : "l"(&g_count) : "memory");
        *sbar = t;
    }
    __syncthreads();
    unsigned t = *sbar;
    unsigned epoch = t / GRID_P + 1u;
    if ((t % GRID_P) == GRID_P - 1u) {          // this block is the releaser
        if (tid < GRID_P)
            asm volatile("st.release.gpu.global.u32 [%0], %1;"
                         :: "l"(&g_flag[tid * 32]), "r"(epoch) : "memory");
    }
    if (tid == 0) {
        unsigned v;
        do {
            asm volatile("ld.acquire.gpu.global.u32 %0, [%1];"
                         : "=r"(v) : "l"(&g_flag[bid * 32]) : "memory");
        } while (v < epoch);
    }
    __syncthreads();
}

// per-warp fp32 partials -> block fp32 -> global fp64 atomic (256B-strided dst)
__device__ __forceinline__ void blockAcc(float* sacc, const float a[8],
                                         int lane, int warp, int tid,
                                         double* gdst) {
    float4* dst = (float4*)(sacc + warp * NK);
    dst[lane]      = make_float4(a[0], a[1], a[2], a[3]);
    dst[32 + lane] = make_float4(a[4], a[5], a[6], a[7]);
    __syncthreads();
    if (tid < NK) {
        float s = 0.f;
#pragma unroll
        for (int w = 0; w < WARPS_P; w++) s += sacc[w * NK + tid];
        atomicAdd(&gdst[tid * GP], (double)s);
    }
}

// fwd: c[b]=sum u*E; r=1/c stored; Rout[k] += E*(r/B). E retained in regs.
__device__ __forceinline__ void fwdBody(const float* sE, const float* su,
                                        float* svf, int nrows, double* Rout,
                                        float* sacc, int lane, int warp, int tid) {
    float4 u0 = ((const float4*)su)[lane];
    float4 u1 = ((const float4*)su)[32 + lane];
    float a[8];
#pragma unroll
    for (int i = 0; i < 8; i++) a[i] = 0.f;
    for (int lr0 = warp * CHUNK; lr0 < nrows; lr0 += STRIDE) {
        float4 E0[CHUNK], E1[CHUNK];
        float c[CHUNK];
#pragma unroll
        for (int i = 0; i < CHUNK; i++) {
            if (lr0 + i < nrows) {
                const float4* row = (const float4*)(sE + (lr0 + i) * NK);
                E0[i] = row[lane]; E1[i] = row[32 + lane];
                c[i] = E0[i].x*u0.x + E0[i].y*u0.y + E0[i].z*u0.z + E0[i].w*u0.w
                     + E1[i].x*u1.x + E1[i].y*u1.y + E1[i].z*u1.z + E1[i].w*u1.w;
            } else {
                E0[i] = make_float4(0,0,0,0); E1[i] = E0[i]; c[i] = 1.f;
            }
        }
        bflyN(c, CHUNK);
#pragma unroll
        for (int i = 0; i < CHUNK; i++) {
            float r = frcp(fmaxf(c[i], 1e-37f));
            if (lane == 0 && lr0 + i < nrows) svf[lr0 + i] = r;
            float vf = r * INV_B;
            a[0] += E0[i].x*vf; a[1] += E0[i].y*vf; a[2] += E0[i].z*vf; a[3] += E0[i].w*vf;
            a[4] += E1[i].x*vf; a[5] += E1[i].y*vf; a[6] += E1[i].z*vf; a[7] += E1[i].w*vf;
        }
    }
    blockAcc(sacc, a, lane, warp, tid, Rout);
}

// passC (3rd fwd fused with bwd layer 3), CHUNK2 with E,P retained:
//  c, s = sum u*E{,*P}; r=1/c; v3=r/B; cbar=(s*r)*v3; ub3 += E*(cbar - v3*P)
__device__ __forceinline__ void passCBody(const float* sE, const float* su,
                                          const float* __restrict__ fin, int rs,
                                          int nrows, double* gdst, float* sacc,
                                          int lane, int warp, int tid) {
    float4 u0 = ((const float4*)su)[lane];
    float4 u1 = ((const float4*)su)[32 + lane];
    float a[8];
#pragma unroll
    for (int i = 0; i < 8; i++) a[i] = 0.f;
    for (int lr0 = warp * CHUNK2; lr0 < nrows; lr0 += STRIDE2) {
        float4 E0[CHUNK2], E1[CHUNK2], P0[CHUNK2], P1[CHUNK2];
        float c[CHUNK2], s[CHUNK2];
#pragma unroll
        for (int i = 0; i < CHUNK2; i++) {
            if (lr0 + i < nrows) {
                const float4* row  = (const float4*)(sE + (lr0 + i) * NK);
                const float4* frow = (const float4*)(fin + (size_t)(rs + lr0 + i) * NK);
                E0[i] = row[lane]; E1[i] = row[32 + lane];
                P0[i] = frow[lane]; P1[i] = frow[32 + lane];
                float t00 = E0[i].x*u0.x, t01 = E0[i].y*u0.y,
                      t02 = E0[i].z*u0.z, t03 = E0[i].w*u0.w;
                float t10 = E1[i].x*u1.x, t11 = E1[i].y*u1.y,
                      t12 = E1[i].z*u1.z, t13 = E1[i].w*u1.w;
                c[i] = t00+t01+t02+t03 + t10+t11+t12+t13;
                s[i] = t00*P0[i].x + t01*P0[i].y + t02*P0[i].z + t03*P0[i].w
                     + t10*P1[i].x + t11*P1[i].y + t12*P1[i].z + t13*P1[i].w;
            } else {
                E0[i] = make_float4(0,0,0,0); E1[i] = E0[i];
                P0[i] = E0[i]; P1[i] = E0[i];
                c[i] = 1.f; s[i] = 0.f;
            }
        }
        bflyN(c, CHUNK2);
        bflyN(s, CHUNK2);
#pragma unroll
        for (int i = 0; i < CHUNK2; i++) {
            float r = frcp(fmaxf(c[i], 1e-37f));
            float v3f = r * INV_B;
            float cbf = (s[i] * r) * v3f;     // = B*v3^2*s, overflow-safe order
            a[0] += E0[i].x*(cbf - v3f*P0[i].x); a[1] += E0[i].y*(cbf - v3f*P0[i].y);
            a[2] += E0[i].z*(cbf - v3f*P0[i].z); a[3] += E0[i].w*(cbf - v3f*P0[i].w);
            a[4] += E1[i].x*(cbf - v3f*P1[i].x); a[5] += E1[i].y*(cbf - v3f*P1[i].y);
            a[6] += E1[i].z*(cbf - v3f*P1[i].z); a[7] += E1[i].w*(cbf - v3f*P1[i].w);
        }
    }
    blockAcc(sacc, a, lane, warp, tid, gdst);
}

// bwd layer: t[b]=sum rb*E; cb=-(t*r)*(r/B); ub_out += E*cb. E retained.
__device__ __forceinline__ void bwdBody(const float* sE, const float* su,
                                        const float* svf, int nrows, double* gdst,
                                        float* sacc, int lane, int warp, int tid) {
    float4 b0 = ((const float4*)su)[lane];
    float4 b1 = ((const float4*)su)[32 + lane];
    float a[8];
#pragma unroll
    for (int i = 0; i < 8; i++) a[i] = 0.f;
    for (int lr0 = warp * CHUNK; lr0 < nrows; lr0 += STRIDE) {
        float4 E0[CHUNK], E1[CHUNK];
        float t[CHUNK];
#pragma unroll
        for (int i = 0; i < CHUNK; i++) {
            if (lr0 + i < nrows) {
                const float4* row = (const float4*)(sE + (lr0 + i) * NK);
                E0[i] = row[lane]; E1[i] = row[32 + lane];
                t[i] = E0[i].x*b0.x + E0[i].y*b0.y + E0[i].z*b0.z + E0[i].w*b0.w
                     + E1[i].x*b1.x + E1[i].y*b1.y + E1[i].z*b1.z + E1[i].w*b1.w;
            } else {
                E0[i] = make_float4(0,0,0,0); E1[i] = E0[i]; t[i] = 0.f;
            }
        }
        bflyN(t, CHUNK);
#pragma unroll
        for (int i = 0; i < CHUNK; i++) {
            float r = (lr0 + i < nrows) ? svf[lr0 + i] : 0.f;
            float cbf = -(t[i] * r) * (r * INV_B);   // = -B*v^2*t
            a[0] += E0[i].x*cbf; a[1] += E0[i].y*cbf; a[2] += E0[i].z*cbf; a[3] += E0[i].w*cbf;
            a[4] += E1[i].x*cbf; a[5] += E1[i].y*cbf; a[6] += E1[i].z*cbf; a[7] += E1[i].w*cbf;
        }
    }
    blockAcc(sacc, a, lane, warp, tid, gdst);
}

// output: Q = E * (B*v3) * u3, fp32; r refined with one fp32 Newton. Retained E.
__device__ __forceinline__ void outBody(const float* sE, const float* su,
                                        float* __restrict__ out, int rs,
                                        int nrows, int lane, int warp) {
    float4 u0 = ((const float4*)su)[lane];
    float4 u1 = ((const float4*)su)[32 + lane];
    for (int lr0 = warp * CHUNK; lr0 < nrows; lr0 += STRIDE) {
        float4 E0[CHUNK], E1[CHUNK];
        float c[CHUNK];
#pragma unroll
        for (int i = 0; i < CHUNK; i++) {
            if (lr0 + i < nrows) {
                const float4* row = (const float4*)(sE + (lr0 + i) * NK);
                E0[i] = row[lane]; E1[i] = row[32 + lane];
                c[i] = E0[i].x*u0.x + E0[i].y*u0.y + E0[i].z*u0.z + E0[i].w*u0.w
                     + E1[i].x*u1.x + E1[i].y*u1.y + E1[i].z*u1.z + E1[i].w*u1.w;
            } else {
                E0[i] = make_float4(0,0,0,0); E1[i] = E0[i]; c[i] = 1.f;
            }
        }
        bflyN(c, CHUNK);
#pragma unroll
        for (int i = 0; i < CHUNK; i++) {
            int lr = lr0 + i;
            if (lr < nrows) {
                float cc = fmaxf(c[i], 1e-37f);
                float r0 = frcp(cc);
                float bs = r0 * (2.0f - cc * r0);  // refined 1/c = B*v3
                float4 o0, o1;
                o0.x = (E0[i].x*bs)*u0.x; o0.y = (E0[i].y*bs)*u0.y;
                o0.z = (E0[i].z*bs)*u0.z; o0.w = (E0[i].w*bs)*u0.w;
                o1.x = (E1[i].x*bs)*u1.x; o1.y = (E1[i].y*bs)*u1.y;
                o1.z = (E1[i].z*bs)*u1.z; o1.w = (E1[i].w*bs)*u1.w;
                float4* orow = (float4*)(out + (size_t)(rs + lr) * NK);
                orow[lane] = o0;
                orow[32 + lane] = o1;
            }
        }
    }
}

__global__ void __launch_bounds__(BLOCK_P, 1)
sinkhorn_persist(const float* __restrict__ fin, const float* __restrict__ win,
                 float* __restrict__ out) {
    extern __shared__ char smem[];
    double*   sred = (double*)(smem + OFF_RED);
    double*   sK2  = (double*)(smem + OFF_K2);
    double*   sR1  = (double*)(smem + OFF_R1);
    double*   sscl = (double*)(smem + OFF_SCL);
    unsigned* sbar = (unsigned*)(smem + OFF_BARS);
    float*    sw   = (float*) (smem + OFF_W);
    float*    sbuf = (float*) (smem + OFF_BUF);
    float*    sv1  = (float*) (smem + OFF_V1);
    float*    sv2  = (float*) (smem + OFF_V2);
    float*    su   = (float*) (smem + OFF_U);
    float*    sacc = (float*) (smem + OFF_ACC);
    float*    sE   = (float*) (smem + OFF_E);

    const int tid  = threadIdx.x;
    const int lane = tid & 31, warp = tid >> 5;
    const int bid  = blockIdx.x;
    const int rs = (NB * bid) / GRID_P;
    const int re = (NB * (bid + 1)) / GRID_P;
    const int nrows = re - rs;

    // ---- phase A: zero globals (block 0); load w; softmax(w) -> sK2 (all);
    //      stage raw f into smem E area + column-max partials ----
    if (bid == 0 && tid < NK) {
        __stcg(&g_R1[tid * GP], 0.0);
#pragma unroll
        for (int s2 = 0; s2 < 2; s2++) {
            __stcg(&g_R2[s2][tid * GP], 0.0);  __stcg(&g_R3[s2][tid * GP], 0.0);
            __stcg(&g_ub1[s2][tid * GP], 0.0); __stcg(&g_ub2[s2][tid * GP], 0.0);
            __stcg(&g_ub3[s2][tid * GP], 0.0);
        }
    }
    if (tid < NK) { float wv = win[tid]; sw[tid] = wv; sbuf[tid] = 0.f; su[tid] = wv; }
    __syncthreads();
    if (warp == 0) {
        float m = -3.4e38f;
#pragma unroll
        for (int i = 0; i < 8; i++) m = fmaxf(m, su[lane + 32*i]);
        m = warpRedMaxF(m);
        if (lane == 0) sscl[0] = (double)m;
    }
    __syncthreads();
    {   float m = (float)sscl[0];
        float ex = 0.f;
        if (tid < NK) { ex = expf(sw[tid] - m); sred[tid] = (double)ex; }
        __syncthreads();
        if (warp == 0) {
            double s = 0.0;
#pragma unroll
            for (int i = 0; i < 8; i++) s += sred[lane + 32*i];
            s = warpRedSumD(s);
            if (lane == 0) sscl[0] = s;
        }
        __syncthreads();
        float ssum = (float)sscl[0];
        if (tid < NK) sK2[tid] = (double)(ex / ssum);
    }
    {   // stage f into smem + column max (thread = (col, row-half))
        int col = tid & 255, half = tid >> 8;
        float mx = -3.4e38f;
        for (int r = rs + half; r < re; r += 2) {
            float f = fin[(size_t)r * NK + col];
            sE[(r - rs) * NK + col] = f;
            mx = fmaxf(mx, f);
        }
        atomicMax(&g_cmax[col * GPC], encf(mx));   // idempotent across replays
    }
    gridBar(sbar, tid, bid);

    // ---- phase B: E' = exp((f-colmax)*20) in place; R1 = colsum ----
    {
        int col = tid & 255, half = tid >> 8;
        float Mt = decf(__ldcg(&g_cmax[col * GPC]));
        float r1p = 0.f;
        for (int r = rs + half; r < re; r += 2) {
            float e = expf((sE[(r - rs) * NK + col] - Mt) * 20.0f);
            sE[(r - rs) * NK + col] = e;
            r1p += e;
        }
        atomicAdd(&g_R1[col * GP], (double)r1p);
    }
    gridBar(sbar, tid, bid);
    if (tid < NK) sR1[tid] = __ldcg(&g_R1[tid * GP]);
    __syncthreads();

    // ---- outer loop ----
    for (int it = 0; it < N_OUTER; ++it) {
        const int s = it & 1;
        const bool last = (it == N_OUTER - 1);

        // fwd1: u1 = K2/R1 -> sv1, R2[s]
        if (tid < NK) su[tid] = (float)sK2[tid] / (float)sR1[tid];
        __syncthreads();
        fwdBody(sE, su, sv1, nrows, g_R2[s], sacc, lane, warp, tid);
        gridBar(sbar, tid, bid);

        // zero next iteration's accumulator slot (block 0; double-buffered:
        // slot s^1 was last read before this barrier, next written 2 bars later)
        if (bid == 0 && !last && tid < NK) {
            int t2 = s ^ 1;
            __stcg(&g_R2[t2][tid * GP], 0.0);  __stcg(&g_R3[t2][tid * GP], 0.0);
            __stcg(&g_ub1[t2][tid * GP], 0.0); __stcg(&g_ub2[t2][tid * GP], 0.0);
            __stcg(&g_ub3[t2][tid * GP], 0.0);
        }

        // fwd2: u2 = K2/R2 -> sv2, R3[s]
        if (tid < NK) su[tid] = (float)sK2[tid] / (float)__ldcg(&g_R2[s][tid * GP]);
        __syncthreads();
        fwdBody(sE, su, sv2, nrows, g_R3[s], sacc, lane, warp, tid);
        gridBar(sbar, tid, bid);

        if (!last) {
            // passC: u3 = K2/R3 -> ub3[s]
            if (tid < NK) su[tid] = (float)sK2[tid] / (float)__ldcg(&g_R3[s][tid * GP]);
            __syncthreads();
            passCBody(sE, su, fin, rs, nrows, g_ub3[s], sacc, lane, warp, tid);
            gridBar(sbar, tid, bid);

            // bwd layer 2: rb = -ub3*K2/R3^2 (K-side DP), uses sv2 -> ub2[s]
            if (tid < NK) {
                double R = __ldcg(&g_R3[s][tid * GP]);
                double rd = (double)frcp((float)R);
                su[tid] = (float)((-__ldcg(&g_ub3[s][tid * GP]) * sK2[tid] * rd) * rd);
            }
            __syncthreads();
            bwdBody(sE, su, sv2, nrows, g_ub2[s], sacc, lane, warp, tid);
            gridBar(sbar, tid, bid);

            // bwd layer 1: rb = -ub2*K2/R2^2, uses sv1 -> ub1[s]
            if (tid < NK) {
                double R = __ldcg(&g_R2[s][tid * GP]);
                double rd = (double)frcp((float)R);
                su[tid] = (float)((-__ldcg(&g_ub2[s][tid * GP]) * sK2[tid] * rd) * rd);
            }
            __syncthreads();
            bwdBody(sE, su, sv1, nrows, g_ub1[s], sacc, lane, warp, tid);
            gridBar(sbar, tid, bid);

            // ---- SGD update, redundant per block, warp-reduced ----
            double K2j = 0.0, kb = 0.0;
            if (tid < NK) {
                K2j = sK2[tid];
                kb = __ldcg(&g_ub1[s][tid * GP]) * rcpd(sR1[tid])
                   + __ldcg(&g_ub2[s][tid * GP]) * rcpd(__ldcg(&g_R2[s][tid * GP]))
                   + __ldcg(&g_ub3[s][tid * GP]) * rcpd(__ldcg(&g_R3[s][tid * GP]));
                sred[tid] = kb * K2j;
            }
            __syncthreads();
            if (warp == 0) {
                double d = 0.0;
#pragma unroll
                for (int i = 0; i < 8; i++) d += sred[lane + 32*i];
                d = warpRedSumD(d);
                if (lane == 0) sscl[0] = d;
            }
            __syncthreads();
            double dot = sscl[0];
            float gf = 0.f;
            if (tid < NK) {
                double g = K2j*(kb - dot) + 5.0*(K2j*(1.0/256.0) - (1.0/65536.0));
                gf = (float)g;
                sred[tid] = (double)gf * (double)gf;
            }
            __syncthreads();
            if (warp == 0) {
                double d = 0.0;
#pragma unroll
                for (int i = 0; i < 8; i++) d += sred[lane + 32*i];
                d = warpRedSumD(d);
                if (lane == 0) sscl[0] = sqrt(d);
            }
            __syncthreads();
            float norm = (float)sscl[0];
            if (tid < NK) {
                gf *= fminf(1.0f, 1.0f/(norm + 1e-6f));
                float bf = 0.99f*sbuf[tid] + gf; sbuf[tid] = bf;
                float wv = sw[tid] - 0.1f*bf;    sw[tid]   = wv;
                su[tid] = wv;
            }
            __syncthreads();
            if (warp == 0) {
                float m = -3.4e38f;
#pragma unroll
                for (int i = 0; i < 8; i++) m = fmaxf(m, su[lane + 32*i]);
                m = warpRedMaxF(m);
                if (lane == 0) sscl[0] = (double)m;
            }
            __syncthreads();
            float m = (float)sscl[0];
            float ex = 0.f;
            if (tid < NK) { ex = expf(sw[tid] - m); sred[tid] = (double)ex; }
            __syncthreads();
            if (warp == 0) {
                double d = 0.0;
#pragma unroll
                for (int i = 0; i < 8; i++) d += sred[lane + 32*i];
                d = warpRedSumD(d);
                if (lane == 0) sscl[0] = d;
            }
            __syncthreads();
            float ssum = (float)sscl[0];
            if (tid < NK) sK2[tid] = (double)(ex / ssum);
            __syncthreads();
        } else {
            // final: Q uses pre-update w
            if (tid < NK) su[tid] = (float)sK2[tid] / (float)__ldcg(&g_R3[s][tid * GP]);
            __syncthreads();
            outBody(sE, su, out, rs, nrows, lane, warp);
        }
    }
}

// ---------------------------------------------------------------------------
extern "C" void kernel_launch(void* const* d_in, const int* in_sizes, int n_in,
                              void* d_out, int out_size) {
    const float* fin = nullptr;
    const float* win = nullptr;
    for (int i = 0; i < n_in; i++) {
        if (in_sizes[i] == NB*NK)   fin = (const float*)d_in[i];
        else if (in_sizes[i] == NK) win = (const float*)d_in[i];
    }
    if (!fin) fin = (const float*)d_in[0];
    if (!win) win = (const float*)d_in[1];
    float* out = (float*)d_out;

    cudaFuncSetAttribute(sinkhorn_persist,
                         cudaFuncAttributeMaxDynamicSharedMemorySize, SMEM_TOTAL);
    sinkhorn_persist<<<GRID_P, BLOCK_P, SMEM_TOTAL>>>(fin, win, out);
}